// round 11
// baseline (speedup 1.0000x reference)
#include <cuda_runtime.h>
#include <cstdint>

namespace {

constexpr int kB = 16, kC = 64, kH = 128, kW = 128;
constexpr int PX = 68;    // pitch, w-major [128 x 64] Q/K tiles; 68 % 32 == 4
constexpr int PV = 132;   // pitch, c-major [64 x 128] V tiles; 132 % 32 == 4
constexpr int PW = 136;   // pitch, c-major [64 x 128] x tiles; 136 % 32 == 8
constexpr int NTHR = 512;
constexpr int PLANE = kH * kW;
// E: 128x128, pitch 128, XOR-swizzled: word(r,c) = r*128 + (c ^ 8*(r&3) ^ 4*((r>>2)&1))
constexpr int SMEM_FLOATS =
    2 * 64 * PW + 2 * 128 * PX + 128 * 128 + 2 * 512 + 4 * 128 + 4 * 64 + 2 * 128 + 128;

__device__ __forceinline__ uint32_t f2t(float x) {
  uint32_t r;
  asm("cvt.rna.tf32.f32 %0, %1;" : "=r"(r) : "f"(x));
  return r;
}
__device__ __forceinline__ float tround(float x) { return __uint_as_float(f2t(x)); }
__device__ __forceinline__ uint32_t fu(float x) { return __float_as_uint(x); }

__device__ __forceinline__ void mma8(float* c, uint32_t a0, uint32_t a1, uint32_t a2,
                                     uint32_t a3, uint32_t b0, uint32_t b1) {
  asm volatile(
      "mma.sync.aligned.m16n8k8.row.col.f32.tf32.tf32.f32 "
      "{%0,%1,%2,%3},{%4,%5,%6,%7},{%8,%9},{%0,%1,%2,%3};"
      : "+f"(c[0]), "+f"(c[1]), "+f"(c[2]), "+f"(c[3])
      : "r"(a0), "r"(a1), "r"(a2), "r"(a3), "r"(b0), "r"(b1));
}

// Q/K gemm: C[128][64] = A @ (W*g)^T with LN epilogue. A c-major smem [c][PW];
// W direct from GMEM (L2-hot), gamma folded per-element (tround matches t1).
// 16 warps, 4(m)x4(n) grid, 32x16 tiles (R6-proven shape).
__device__ __forceinline__ void gemm_qk(
    const float* __restrict__ A, const float* __restrict__ Wsrc,
    const float* __restrict__ gs, float* __restrict__ C,
    int wid, int qr, int qc, const float* __restrict__ mean,
    const float* __restrict__ rstd, const float* __restrict__ t1,
    const float* __restrict__ t2) {
  const int r0 = (wid & 3) * 32;
  const int c0 = (wid >> 2) * 16;
  float acc[2][2][4];
#pragma unroll
  for (int mi = 0; mi < 2; mi++)
#pragma unroll
    for (int nj = 0; nj < 2; nj++)
#pragma unroll
      for (int e = 0; e < 4; e++) acc[mi][nj][e] = 0.f;

#pragma unroll
  for (int k0 = 0; k0 < 64; k0 += 8) {
    uint32_t af[2][4];
#pragma unroll
    for (int mi = 0; mi < 2; mi++) {
      const float* ap = A + (k0 + qc) * PW + r0 + mi * 16 + qr;
      af[mi][0] = f2t(ap[0]);
      af[mi][1] = f2t(ap[8]);
      af[mi][2] = f2t(ap[4 * PW]);
      af[mi][3] = f2t(ap[4 * PW + 8]);
    }
    const float gv0 = gs[k0 + qc];
    const float gv4 = gs[k0 + qc + 4];
    uint32_t bf[2][2];
#pragma unroll
    for (int nj = 0; nj < 2; nj++) {
      const float* wp = Wsrc + (c0 + nj * 8 + qr) * 64 + k0 + qc;
      bf[nj][0] = f2t(wp[0] * gv0);
      bf[nj][1] = f2t(wp[4] * gv4);
    }
#pragma unroll
    for (int mi = 0; mi < 2; mi++)
#pragma unroll
      for (int nj = 0; nj < 2; nj++)
        mma8(acc[mi][nj], af[mi][0], af[mi][1], af[mi][2], af[mi][3], bf[nj][0], bf[nj][1]);
  }

#pragma unroll
  for (int mi = 0; mi < 2; mi++) {
    const int ra = r0 + mi * 16 + qr;
#pragma unroll
    for (int nj = 0; nj < 2; nj++) {
      const int cc = c0 + nj * 8 + 2 * qc;
      const float m0 = mean[ra], rs0 = rstd[ra];
      const float m1 = mean[ra + 8], rs1 = rstd[ra + 8];
      const float ta = t1[cc], tb = t1[cc + 1];
      const float ua = t2[cc], ub = t2[cc + 1];
      const float v0 = rs0 * (acc[mi][nj][0] - m0 * ta) + ua;
      const float v1 = rs0 * (acc[mi][nj][1] - m0 * tb) + ub;
      const float v2 = rs1 * (acc[mi][nj][2] - m1 * ta) + ua;
      const float v3 = rs1 * (acc[mi][nj][3] - m1 * tb) + ub;
      *(float2*)&C[ra * PX + cc] = make_float2(tround(v0), tround(v1));
      *(float2*)&C[(ra + 8) * PX + cc] = make_float2(tround(v2), tround(v3));
    }
  }
}

// V gemm: C (c-major [c][PV]) = A @ W^T, raw weights from GMEM. Same shape.
__device__ __forceinline__ void gemm_v(
    const float* __restrict__ A, const float* __restrict__ Wsrc,
    float* __restrict__ C, int wid, int qr, int qc) {
  const int r0 = (wid & 3) * 32;
  const int c0 = (wid >> 2) * 16;
  float acc[2][2][4];
#pragma unroll
  for (int mi = 0; mi < 2; mi++)
#pragma unroll
    for (int nj = 0; nj < 2; nj++)
#pragma unroll
      for (int e = 0; e < 4; e++) acc[mi][nj][e] = 0.f;

#pragma unroll
  for (int k0 = 0; k0 < 64; k0 += 8) {
    uint32_t af[2][4];
#pragma unroll
    for (int mi = 0; mi < 2; mi++) {
      const float* ap = A + (k0 + qc) * PW + r0 + mi * 16 + qr;
      af[mi][0] = f2t(ap[0]);
      af[mi][1] = f2t(ap[8]);
      af[mi][2] = f2t(ap[4 * PW]);
      af[mi][3] = f2t(ap[4 * PW + 8]);
    }
    uint32_t bf[2][2];
#pragma unroll
    for (int nj = 0; nj < 2; nj++) {
      const float* wp = Wsrc + (c0 + nj * 8 + qr) * 64 + k0 + qc;
      bf[nj][0] = f2t(wp[0]);
      bf[nj][1] = f2t(wp[4]);
    }
#pragma unroll
    for (int mi = 0; mi < 2; mi++)
#pragma unroll
      for (int nj = 0; nj < 2; nj++)
        mma8(acc[mi][nj], af[mi][0], af[mi][1], af[mi][2], af[mi][3], bf[nj][0], bf[nj][1]);
  }

#pragma unroll
  for (int mi = 0; mi < 2; mi++) {
    const int ra = r0 + mi * 16 + qr;
#pragma unroll
    for (int nj = 0; nj < 2; nj++) {
      const int cc = c0 + nj * 8 + 2 * qc;
      C[cc * PV + ra] = tround(acc[mi][nj][0]);
      C[(cc + 1) * PV + ra] = tround(acc[mi][nj][1]);
      C[cc * PV + ra + 8] = tround(acc[mi][nj][2]);
      C[(cc + 1) * PV + ra + 8] = tround(acc[mi][nj][3]);
    }
  }
}

// E = exp(Q K^T / 8) -> swizzled E + per-tile row/col partials. 16 warps, 4x4.
__device__ __forceinline__ void gemm_s(
    const float* __restrict__ Q, const float* __restrict__ K, float* __restrict__ E,
    float* __restrict__ rowp, float* __restrict__ colp, int wid, int qr, int qc,
    int swm) {
  const int r0 = (wid & 3) * 32;
  const int c0 = (wid >> 2) * 32;
  float acc[2][4][4];
#pragma unroll
  for (int mi = 0; mi < 2; mi++)
#pragma unroll
    for (int nj = 0; nj < 4; nj++)
#pragma unroll
      for (int e = 0; e < 4; e++) acc[mi][nj][e] = 0.f;

#pragma unroll
  for (int k0 = 0; k0 < 64; k0 += 8) {
    uint32_t af[2][4];
#pragma unroll
    for (int mi = 0; mi < 2; mi++) {
      const float* ap = Q + (r0 + mi * 16 + qr) * PX + k0 + qc;
      af[mi][0] = fu(ap[0]);
      af[mi][1] = fu(ap[8 * PX]);
      af[mi][2] = fu(ap[4]);
      af[mi][3] = fu(ap[8 * PX + 4]);
    }
    uint32_t bf[4][2];
#pragma unroll
    for (int nj = 0; nj < 4; nj++) {
      const float* bp = K + (c0 + nj * 8 + qr) * PX + k0 + qc;
      bf[nj][0] = fu(bp[0]);
      bf[nj][1] = fu(bp[4]);
    }
#pragma unroll
    for (int mi = 0; mi < 2; mi++)
#pragma unroll
      for (int nj = 0; nj < 4; nj++)
        mma8(acc[mi][nj], af[mi][0], af[mi][1], af[mi][2], af[mi][3], bf[nj][0], bf[nj][1]);
  }

  float rs0[2] = {0.f, 0.f}, rs1[2] = {0.f, 0.f};
  float cs0[4] = {0.f, 0.f, 0.f, 0.f}, cs1[4] = {0.f, 0.f, 0.f, 0.f};
#pragma unroll
  for (int mi = 0; mi < 2; mi++) {
    const int ra = r0 + mi * 16 + qr;
#pragma unroll
    for (int nj = 0; nj < 4; nj++) {
      const int cc = c0 + nj * 8 + 2 * qc;
      const int cS = cc ^ swm;
      const float e0 = tround(__expf(0.125f * acc[mi][nj][0]));
      const float e1 = tround(__expf(0.125f * acc[mi][nj][1]));
      const float e2 = tround(__expf(0.125f * acc[mi][nj][2]));
      const float e3 = tround(__expf(0.125f * acc[mi][nj][3]));
      *(float2*)&E[ra * 128 + cS] = make_float2(e0, e1);
      *(float2*)&E[(ra + 8) * 128 + cS] = make_float2(e2, e3);
      rs0[mi] += e0 + e1;
      rs1[mi] += e2 + e3;
      cs0[nj] += e0 + e2;
      cs1[nj] += e1 + e3;
    }
  }
#pragma unroll
  for (int mi = 0; mi < 2; mi++) {
    rs0[mi] += __shfl_xor_sync(0xffffffffu, rs0[mi], 1);
    rs0[mi] += __shfl_xor_sync(0xffffffffu, rs0[mi], 2);
    rs1[mi] += __shfl_xor_sync(0xffffffffu, rs1[mi], 1);
    rs1[mi] += __shfl_xor_sync(0xffffffffu, rs1[mi], 2);
  }
  if (qc == 0) {
    float* rp = rowp + (wid >> 2) * 128;
#pragma unroll
    for (int mi = 0; mi < 2; mi++) {
      rp[r0 + mi * 16 + qr] = rs0[mi];
      rp[r0 + mi * 16 + qr + 8] = rs1[mi];
    }
  }
#pragma unroll
  for (int nj = 0; nj < 4; nj++) {
    cs0[nj] += __shfl_xor_sync(0xffffffffu, cs0[nj], 4);
    cs0[nj] += __shfl_xor_sync(0xffffffffu, cs0[nj], 8);
    cs0[nj] += __shfl_xor_sync(0xffffffffu, cs0[nj], 16);
    cs1[nj] += __shfl_xor_sync(0xffffffffu, cs1[nj], 4);
    cs1[nj] += __shfl_xor_sync(0xffffffffu, cs1[nj], 8);
    cs1[nj] += __shfl_xor_sync(0xffffffffu, cs1[nj], 16);
  }
  if (qr == 0) {
    float* cp = colp + (wid & 3) * 128;
#pragma unroll
    for (int nj = 0; nj < 4; nj++) {
      cp[c0 + nj * 8 + 2 * qc] = cs0[nj];
      cp[c0 + nj * 8 + 2 * qc + 1] = cs1[nj];
    }
  }
}

// XL[c][w] += invrow[w] * (E @ V2)[w][c]. 16 warps, 4(w)x4(c), 32x16, K=128.
__device__ __forceinline__ void gemm_out_l(
    const float* __restrict__ E, const float* __restrict__ V2, float* __restrict__ XL,
    const float* __restrict__ invrow, int wid, int qr, int qc, int swm) {
  const int r0 = (wid & 3) * 32;
  const int c0 = (wid >> 2) * 16;
  float acc[2][2][4];
#pragma unroll
  for (int mi = 0; mi < 2; mi++)
#pragma unroll
    for (int nj = 0; nj < 2; nj++)
#pragma unroll
      for (int e = 0; e < 4; e++) acc[mi][nj][e] = 0.f;

#pragma unroll
  for (int k0 = 0; k0 < 128; k0 += 8) {
    const int col = (k0 + qc) ^ swm;
    uint32_t af[2][4];
#pragma unroll
    for (int mi = 0; mi < 2; mi++) {
      const int r = r0 + mi * 16 + qr;
      af[mi][0] = fu(E[r * 128 + col]);
      af[mi][1] = fu(E[(r + 8) * 128 + col]);
      af[mi][2] = fu(E[r * 128 + (col ^ 4)]);
      af[mi][3] = fu(E[(r + 8) * 128 + (col ^ 4)]);
    }
    uint32_t bf[2][2];
#pragma unroll
    for (int nj = 0; nj < 2; nj++) {
      const float* bp = V2 + (c0 + nj * 8 + qr) * PV + k0 + qc;
      bf[nj][0] = fu(bp[0]);
      bf[nj][1] = fu(bp[4]);
    }
#pragma unroll
    for (int mi = 0; mi < 2; mi++)
#pragma unroll
      for (int nj = 0; nj < 2; nj++)
        mma8(acc[mi][nj], af[mi][0], af[mi][1], af[mi][2], af[mi][3], bf[nj][0], bf[nj][1]);
  }

#pragma unroll
  for (int mi = 0; mi < 2; mi++) {
    const int ra = r0 + mi * 16 + qr;
    const float ir0 = invrow[ra], ir1 = invrow[ra + 8];
#pragma unroll
    for (int nj = 0; nj < 2; nj++) {
      const int cc = c0 + nj * 8 + 2 * qc;
      XL[cc * PW + ra] += acc[mi][nj][0] * ir0;
      XL[(cc + 1) * PW + ra] += acc[mi][nj][1] * ir0;
      XL[cc * PW + ra + 8] += acc[mi][nj][2] * ir1;
      XL[(cc + 1) * PW + ra + 8] += acc[mi][nj][3] * ir1;
    }
  }
}

// out_h^T = V1^T @ E. 16 warps, 4(c)x4(w) grid, 16x32 tiles. V1 c-major; E swizzled.
__device__ __forceinline__ void gemm_out_h(
    const float* __restrict__ E, const float* __restrict__ V1, float* __restrict__ XH,
    const float* __restrict__ invcol, int wid, int qr, int qc) {
  const int r0 = (wid & 3) * 16;   // c dimension (64)
  const int c0 = (wid >> 2) * 32;  // w dimension (128)
  float acc[4][4];
#pragma unroll
  for (int nj = 0; nj < 4; nj++)
#pragma unroll
    for (int e = 0; e < 4; e++) acc[nj][e] = 0.f;

  const int sw1 = 8 * qc;
#pragma unroll
  for (int k0 = 0; k0 < 128; k0 += 8) {
    const int rr = r0 + qr;
    const float* ap = V1 + rr * PV + k0 + qc;
    uint32_t a0 = fu(ap[0]);
    uint32_t a1 = fu(ap[8 * PV]);
    uint32_t a2 = fu(ap[4]);
    uint32_t a3 = fu(ap[8 * PV + 4]);
    const int rowA = (k0 + qc) * 128;
    const int rowB = (k0 + qc + 4) * 128;
    uint32_t bf[4][2];
#pragma unroll
    for (int nj = 0; nj < 4; nj++) {
      const int cc = c0 + nj * 8 + qr;
      bf[nj][0] = fu(E[rowA + (cc ^ sw1)]);
      bf[nj][1] = fu(E[rowB + (cc ^ sw1 ^ 4)]);
    }
#pragma unroll
    for (int nj = 0; nj < 4; nj++)
      mma8(acc[nj], a0, a1, a2, a3, bf[nj][0], bf[nj][1]);
  }

  const int ra = r0 + qr;  // c
#pragma unroll
  for (int nj = 0; nj < 4; nj++) {
    const int w0 = c0 + nj * 8 + 2 * qc;
    const int w1 = w0 + 1;
    XH[ra * PW + w0] += acc[nj][0] * invcol[w0];
    XH[ra * PW + w1] += acc[nj][1] * invcol[w1];
    XH[(ra + 8) * PW + w0] += acc[nj][2] * invcol[w0];
    XH[(ra + 8) * PW + w1] += acc[nj][3] * invcol[w1];
  }
}

__global__ __launch_bounds__(NTHR)
void scam_kernel(const float* __restrict__ x_l, const float* __restrict__ x_h,
                 const float* __restrict__ g1, const float* __restrict__ b1,
                 const float* __restrict__ g2, const float* __restrict__ b2,
                 const float* __restrict__ Wq, const float* __restrict__ Wk,
                 const float* __restrict__ Wv1, const float* __restrict__ Wv2,
                 float* __restrict__ out_l, float* __restrict__ out_h) {
  extern __shared__ float sm[];
  float* XL = sm;                    // [64][PW] c-major fp32 residual + out stage
  float* XH = XL + 64 * PW;
  float* QV1 = XH + 64 * PW;         // Q w-major [128][PX], then V1 c-major [64][PV]
  float* KV2 = QV1 + 128 * PX;       // K, then V2
  float* Ebuf = KV2 + 128 * PX;      // [128][128] swizzled exp(attn)
  float* rowp = Ebuf + 128 * 128;    // [4][128]
  float* colp = rowp + 512;          // [4][128]
  float* meanl = colp + 512;
  float* rstdl = meanl + 128;
  float* meanh = rstdl + 128;
  float* rstdh = meanh + 128;
  float* t1q = rstdh + 128;
  float* t2q = t1q + 64;
  float* t1k = t2q + 64;
  float* t2k = t1k + 64;
  float* invrow = t2k + 64;
  float* invcol = invrow + 128;
  float* gsq = invcol + 128;  // gamma1 staged [64]
  float* gsk = gsq + 64;      // gamma2 staged [64]

  const int tid = threadIdx.x;
  const int lane = tid & 31;
  const int wid = tid >> 5;
  const int qr = lane >> 2;
  const int qc = lane & 3;
  const int swm = ((qr & 3) << 3) | (((qr >> 2) & 1) << 2);
  const int bh = blockIdx.x;
  const int b = bh >> 7;
  const int h = bh & 127;
  const size_t planeoff = ((size_t)b * kC * kH + (size_t)h) * kW;

  // ---- P1: stage x (c-major float4, conflict-free) + gamma ----
  for (int i = tid; i < kC * (kW / 4); i += NTHR) {
    const int c = i >> 5;
    const int w4 = (i & 31) * 4;
    const size_t goff = planeoff + (size_t)c * PLANE + w4;
    *(float4*)(XL + c * PW + w4) = *(const float4*)(x_l + goff);
    *(float4*)(XH + c * PW + w4) = *(const float4*)(x_h + goff);
  }
  if (tid < 64)        gsq[tid] = g1[tid];
  else if (tid < 128)  gsk[tid - 64] = g2[tid - 64];
  __syncthreads();

  // ---- P2: LN stats (2 thr/row) + t1/t2 from GMEM weights ----
  {
    const int rowid = tid >> 1;
    const int r = rowid & 127;
    const int half = tid & 1;
    const float* src = (rowid < 128 ? XL : XH) + half * 32 * PW + r;
    float s = 0.f, s2 = 0.f;
#pragma unroll
    for (int c = 0; c < 32; c++) {
      const float v = src[c * PW];
      s += v;
      s2 = fmaf(v, v, s2);
    }
    s += __shfl_xor_sync(0xffffffffu, s, 1);
    s2 += __shfl_xor_sync(0xffffffffu, s2, 1);
    if (half == 0) {
      const float m = s * (1.f / 64.f);
      const float var = fmaf(-m, m, s2 * (1.f / 64.f));
      const float rs = rsqrtf(var + 1e-5f);
      if (rowid < 128) { meanl[r] = m; rstdl[r] = rs; }
      else             { meanh[r] = m; rstdh[r] = rs; }
    }
  }
  if (tid < 128) {
    const int j = tid & 63;
    const float* Wsrc = (tid < 64) ? Wq : Wk;
    const float* gp = (tid < 64) ? gsq : gsk;
    const float* bp = (tid < 64) ? b1 : b2;
    float s1 = 0.f, s2 = 0.f;
#pragma unroll 8
    for (int c = 0; c < 64; c++) {
      const float raw = Wsrc[j * 64 + c];
      s1 += tround(raw * gp[c]);
      s2 = fmaf(raw, bp[c], s2);
    }
    if (tid < 64) { t1q[j] = s1; t2q[j] = s2; }
    else          { t1k[j] = s1; t2k[j] = s2; }
  }
  __syncthreads();

  // ---- P3: Q then K (back-to-back, no sync between) ----
  gemm_qk(XL, Wq, gsq, QV1, wid, qr, qc, meanl, rstdl, t1q, t2q);
  gemm_qk(XH, Wk, gsk, KV2, wid, qr, qc, meanh, rstdh, t1k, t2k);
  __syncthreads();

  // ---- P4: E = exp(QK^T/8) + in-register row/col partials ----
  gemm_s(QV1, KV2, Ebuf, rowp, colp, wid, qr, qc, swm);
  __syncthreads();

  // ---- P5: inverses; V1 then V2 (V1 overwrites Q, V2 overwrites K) ----
  if (tid < 128) {
    invrow[tid] = 1.f / (rowp[tid] + rowp[128 + tid] + rowp[256 + tid] + rowp[384 + tid]);
  } else if (tid < 256) {
    const int c = tid - 128;
    invcol[c] = 1.f / (colp[c] + colp[128 + c] + colp[256 + c] + colp[384 + c]);
  }
  gemm_v(XL, Wv1, QV1, wid, qr, qc);
  gemm_v(XH, Wv2, KV2, wid, qr, qc);
  __syncthreads();

  // ---- P6: out_l then out_h (smem epilogues into XL/XH) ----
  gemm_out_l(Ebuf, KV2, XL, invrow, wid, qr, qc, swm);
  gemm_out_h(Ebuf, QV1, XH, invcol, wid, qr, qc);
  __syncthreads();

  // ---- P7: writeout (conflict-free LDS.128, coalesced STG) ----
  for (int i = tid; i < kC * (kW / 4); i += NTHR) {
    const int c = i >> 5;
    const int w4 = (i & 31) * 4;
    const size_t goff = planeoff + (size_t)c * PLANE + w4;
    *(float4*)(out_l + goff) = *(const float4*)(XL + c * PW + w4);
    *(float4*)(out_h + goff) = *(const float4*)(XH + c * PW + w4);
  }
}

}  // namespace

extern "C" void kernel_launch(void* const* d_in, const int* in_sizes, int n_in,
                              void* d_out, int out_size) {
  const float* x_l = (const float*)d_in[0];
  const float* x_h = (const float*)d_in[1];
  const float* g1 = (const float*)d_in[2];
  const float* b1 = (const float*)d_in[3];
  const float* g2 = (const float*)d_in[4];
  const float* b2 = (const float*)d_in[5];
  const float* Wq = (const float*)d_in[6];
  const float* Wk = (const float*)d_in[7];
  const float* Wv1 = (const float*)d_in[8];
  const float* Wv2 = (const float*)d_in[9];

  float* out = (float*)d_out;
  float* out_l = out;
  float* out_h = out + (size_t)kB * kC * kH * kW;

  const size_t smem = (size_t)SMEM_FLOATS * sizeof(float);  // ~214 KB
  cudaFuncSetAttribute(scam_kernel, cudaFuncAttributeMaxDynamicSharedMemorySize, (int)smem);
  scam_kernel<<<kB * kH, NTHR, smem>>>(x_l, x_h, g1, b1, g2, b2, Wq, Wk, Wv1, Wv2,
                                       out_l, out_h);
}

// round 13
// speedup vs baseline: 1.6249x; 1.6249x over previous
#include <cuda_runtime.h>
#include <cstdint>

namespace {

constexpr int kB = 16, kC = 64, kH = 128, kW = 128;
constexpr int PX = 68;    // pitch, w-major [128 x 64] Q/K tiles; 68 % 32 == 4
constexpr int PB = 68;    // pitch (uint32 words) for bf16x2 E/V/Et tiles; 68 % 32 == 4
constexpr int PW = 136;   // pitch, c-major [64 x 128] x tiles; 136 % 32 == 8
constexpr int NTHR = 512;
constexpr int PLANE = kH * kW;
constexpr int SMEM_FLOATS =
    2 * 64 * PW + 2 * 128 * PX + 128 * PB + 64 * PX + 2 * 512 + 4 * 128 + 2 * 64 + 2 * 128;

__device__ __forceinline__ uint32_t f2t(float x) {
  uint32_t r;
  asm("cvt.rna.tf32.f32 %0, %1;" : "=r"(r) : "f"(x));
  return r;
}
__device__ __forceinline__ float tround(float x) { return __uint_as_float(f2t(x)); }
__device__ __forceinline__ uint32_t fu(float x) { return __float_as_uint(x); }

// pack two fp32 -> bf16x2 (lo = first/even element, hi = second)
__device__ __forceinline__ uint32_t bfpack(float lo, float hi) {
  uint32_t r;
  asm("cvt.rn.bf16x2.f32 %0, %1, %2;" : "=r"(r) : "f"(hi), "f"(lo));
  return r;
}

// tf32 m16n8k8
__device__ __forceinline__ void mma8(float* c, uint32_t a0, uint32_t a1, uint32_t a2,
                                     uint32_t a3, uint32_t b0, uint32_t b1) {
  asm volatile(
      "mma.sync.aligned.m16n8k8.row.col.f32.tf32.tf32.f32 "
      "{%0,%1,%2,%3},{%4,%5,%6,%7},{%8,%9},{%0,%1,%2,%3};"
      : "+f"(c[0]), "+f"(c[1]), "+f"(c[2]), "+f"(c[3])
      : "r"(a0), "r"(a1), "r"(a2), "r"(a3), "r"(b0), "r"(b1));
}

// bf16 m16n8k16
__device__ __forceinline__ void mma16(float* c, uint32_t a0, uint32_t a1, uint32_t a2,
                                      uint32_t a3, uint32_t b0, uint32_t b1) {
  asm volatile(
      "mma.sync.aligned.m16n8k16.row.col.f32.bf16.bf16.f32 "
      "{%0,%1,%2,%3},{%4,%5,%6,%7},{%8,%9},{%0,%1,%2,%3};"
      : "+f"(c[0]), "+f"(c[1]), "+f"(c[2]), "+f"(c[3])
      : "r"(a0), "r"(a1), "r"(a2), "r"(a3), "r"(b0), "r"(b1));
}

// 64x64 weight fold, fp32->tf32; 512 thr: 8 threads per row.
__device__ __forceinline__ void load_weight_fold(
    const float* __restrict__ Wsrc, const float* __restrict__ g,
    const float* __restrict__ bb, float* __restrict__ WB,
    float* __restrict__ t1, float* __restrict__ t2, int tid) {
  const int j = tid >> 3;
  const int c0 = (tid & 7) * 8;
  float s1 = 0.f, s2 = 0.f;
#pragma unroll
  for (int u = 0; u < 8; u++) {
    const int c = c0 + u;
    const float raw = Wsrc[j * 64 + c];
    const float wf = tround(raw * g[c]);
    WB[j * PX + c] = wf;
    s1 += wf;
    s2 += raw * bb[c];
  }
  s1 += __shfl_xor_sync(0xffffffffu, s1, 1);
  s1 += __shfl_xor_sync(0xffffffffu, s1, 2);
  s1 += __shfl_xor_sync(0xffffffffu, s1, 4);
  s2 += __shfl_xor_sync(0xffffffffu, s2, 1);
  s2 += __shfl_xor_sync(0xffffffffu, s2, 2);
  s2 += __shfl_xor_sync(0xffffffffu, s2, 4);
  if ((tid & 7) == 0) { t1[j] = s1; t2[j] = s2; }
}

__device__ __forceinline__ void load_weight_raw(
    const float* __restrict__ Wsrc, float* __restrict__ WB, int tid) {
  const int j = tid >> 3;
  const int c0 = (tid & 7) * 8;
#pragma unroll
  for (int u = 0; u < 8; u++) WB[j * PX + c0 + u] = tround(Wsrc[j * 64 + c0 + u]);
}

// Q/K gemm: C[128][64] = A @ WB^T, LN epilogue, output w-major [w][PX].
// A c-major [c][PW]. 16 warps, 4(m)x4(n), 32x16 tiles.
__device__ __forceinline__ void gemm_qk(
    const float* __restrict__ A, const float* __restrict__ WB, float* __restrict__ C,
    int wid, int qr, int qc, const float* __restrict__ mean,
    const float* __restrict__ rstd, const float* __restrict__ t1,
    const float* __restrict__ t2) {
  const int r0 = (wid & 3) * 32;
  const int c0 = (wid >> 2) * 16;
  float acc[2][2][4];
#pragma unroll
  for (int mi = 0; mi < 2; mi++)
#pragma unroll
    for (int nj = 0; nj < 2; nj++)
#pragma unroll
      for (int e = 0; e < 4; e++) acc[mi][nj][e] = 0.f;

#pragma unroll
  for (int k0 = 0; k0 < 64; k0 += 8) {
    uint32_t af[2][4];
#pragma unroll
    for (int mi = 0; mi < 2; mi++) {
      const float* ap = A + (k0 + qc) * PW + r0 + mi * 16 + qr;
      af[mi][0] = f2t(ap[0]);
      af[mi][1] = f2t(ap[8]);
      af[mi][2] = f2t(ap[4 * PW]);
      af[mi][3] = f2t(ap[4 * PW + 8]);
    }
    uint32_t bf[2][2];
#pragma unroll
    for (int nj = 0; nj < 2; nj++) {
      const float* bp = WB + (c0 + nj * 8 + qr) * PX + k0 + qc;
      bf[nj][0] = fu(bp[0]);
      bf[nj][1] = fu(bp[4]);
    }
#pragma unroll
    for (int mi = 0; mi < 2; mi++)
#pragma unroll
      for (int nj = 0; nj < 2; nj++)
        mma8(acc[mi][nj], af[mi][0], af[mi][1], af[mi][2], af[mi][3], bf[nj][0], bf[nj][1]);
  }

#pragma unroll
  for (int mi = 0; mi < 2; mi++) {
    const int ra = r0 + mi * 16 + qr;
#pragma unroll
    for (int nj = 0; nj < 2; nj++) {
      const int cc = c0 + nj * 8 + 2 * qc;
      const float m0 = mean[ra], rs0 = rstd[ra];
      const float m1 = mean[ra + 8], rs1 = rstd[ra + 8];
      const float ta = t1[cc], tb = t1[cc + 1];
      const float ua = t2[cc], ub = t2[cc + 1];
      const float v0 = rs0 * (acc[mi][nj][0] - m0 * ta) + ua;
      const float v1 = rs0 * (acc[mi][nj][1] - m0 * tb) + ub;
      const float v2 = rs1 * (acc[mi][nj][2] - m1 * ta) + ua;
      const float v3 = rs1 * (acc[mi][nj][3] - m1 * tb) + ub;
      *(float2*)&C[ra * PX + cc] = make_float2(tround(v0), tround(v1));
      *(float2*)&C[(ra + 8) * PX + cc] = make_float2(tround(v2), tround(v3));
    }
  }
}

// V gemm, OUTPUT-TRANSPOSED: Vt[c_out][w] = sum_k WB[c_out][k] * X[k][w] (tf32).
// Output packed bf16x2 pairs-along-w: V_bf[c][w/2], pitch PB. 16 warps, 4x4.
__device__ __forceinline__ void gemm_vT(
    const float* __restrict__ X, const float* __restrict__ WB,
    uint32_t* __restrict__ Vb, int wid, int qr, int qc) {
  const int r0 = (wid & 3) * 16;   // c_out
  const int c0 = (wid >> 2) * 32;  // w
  float acc[4][4];
#pragma unroll
  for (int nj = 0; nj < 4; nj++)
#pragma unroll
    for (int e = 0; e < 4; e++) acc[nj][e] = 0.f;

#pragma unroll
  for (int k0 = 0; k0 < 64; k0 += 8) {
    const float* ap = WB + (r0 + qr) * PX + k0 + qc;
    uint32_t a0 = fu(ap[0]);
    uint32_t a1 = fu(ap[8 * PX]);
    uint32_t a2 = fu(ap[4]);
    uint32_t a3 = fu(ap[8 * PX + 4]);
    uint32_t bf[4][2];
#pragma unroll
    for (int nj = 0; nj < 4; nj++) {
      const float* bp = X + (k0 + qc) * PW + c0 + nj * 8 + qr;
      bf[nj][0] = f2t(bp[0]);
      bf[nj][1] = f2t(bp[4 * PW]);
    }
#pragma unroll
    for (int nj = 0; nj < 4; nj++)
      mma8(acc[nj], a0, a1, a2, a3, bf[nj][0], bf[nj][1]);
  }

  const int ra = r0 + qr;  // c_out
#pragma unroll
  for (int nj = 0; nj < 4; nj++) {
    const int cw = (c0 >> 1) + nj * 4 + qc;
    Vb[ra * PB + cw] = bfpack(acc[nj][0], acc[nj][1]);
    Vb[(ra + 8) * PB + cw] = bfpack(acc[nj][2], acc[nj][3]);
  }
}

// E = exp(Q K^T / 8) -> bf16x2 Eb[q][v/2] (pairs along v) + row/col partials.
__device__ __forceinline__ void gemm_s(
    const float* __restrict__ Q, const float* __restrict__ K, uint32_t* __restrict__ Eb,
    float* __restrict__ rowp, float* __restrict__ colp, int wid, int qr, int qc) {
  const int r0 = (wid & 3) * 32;
  const int c0 = (wid >> 2) * 32;
  float acc[2][4][4];
#pragma unroll
  for (int mi = 0; mi < 2; mi++)
#pragma unroll
    for (int nj = 0; nj < 4; nj++)
#pragma unroll
      for (int e = 0; e < 4; e++) acc[mi][nj][e] = 0.f;

#pragma unroll
  for (int k0 = 0; k0 < 64; k0 += 8) {
    uint32_t af[2][4];
#pragma unroll
    for (int mi = 0; mi < 2; mi++) {
      const float* ap = Q + (r0 + mi * 16 + qr) * PX + k0 + qc;
      af[mi][0] = fu(ap[0]);
      af[mi][1] = fu(ap[8 * PX]);
      af[mi][2] = fu(ap[4]);
      af[mi][3] = fu(ap[8 * PX + 4]);
    }
    uint32_t bf[4][2];
#pragma unroll
    for (int nj = 0; nj < 4; nj++) {
      const float* bp = K + (c0 + nj * 8 + qr) * PX + k0 + qc;
      bf[nj][0] = fu(bp[0]);
      bf[nj][1] = fu(bp[4]);
    }
#pragma unroll
    for (int mi = 0; mi < 2; mi++)
#pragma unroll
      for (int nj = 0; nj < 4; nj++)
        mma8(acc[mi][nj], af[mi][0], af[mi][1], af[mi][2], af[mi][3], bf[nj][0], bf[nj][1]);
  }

  float rs0[2] = {0.f, 0.f}, rs1[2] = {0.f, 0.f};
  float cs0[4] = {0.f, 0.f, 0.f, 0.f}, cs1[4] = {0.f, 0.f, 0.f, 0.f};
#pragma unroll
  for (int mi = 0; mi < 2; mi++) {
    const int ra = r0 + mi * 16 + qr;
#pragma unroll
    for (int nj = 0; nj < 4; nj++) {
      const int cw = (c0 >> 1) + nj * 4 + qc;
      const float e0 = __expf(0.125f * acc[mi][nj][0]);
      const float e1 = __expf(0.125f * acc[mi][nj][1]);
      const float e2 = __expf(0.125f * acc[mi][nj][2]);
      const float e3 = __expf(0.125f * acc[mi][nj][3]);
      Eb[ra * PB + cw] = bfpack(e0, e1);
      Eb[(ra + 8) * PB + cw] = bfpack(e2, e3);
      rs0[mi] += e0 + e1;
      rs1[mi] += e2 + e3;
      cs0[nj] += e0 + e2;
      cs1[nj] += e1 + e3;
    }
  }
#pragma unroll
  for (int mi = 0; mi < 2; mi++) {
    rs0[mi] += __shfl_xor_sync(0xffffffffu, rs0[mi], 1);
    rs0[mi] += __shfl_xor_sync(0xffffffffu, rs0[mi], 2);
    rs1[mi] += __shfl_xor_sync(0xffffffffu, rs1[mi], 1);
    rs1[mi] += __shfl_xor_sync(0xffffffffu, rs1[mi], 2);
  }
  if (qc == 0) {
    float* rp = rowp + (wid >> 2) * 128;
#pragma unroll
    for (int mi = 0; mi < 2; mi++) {
      rp[r0 + mi * 16 + qr] = rs0[mi];
      rp[r0 + mi * 16 + qr + 8] = rs1[mi];
    }
  }
#pragma unroll
  for (int nj = 0; nj < 4; nj++) {
    cs0[nj] += __shfl_xor_sync(0xffffffffu, cs0[nj], 4);
    cs0[nj] += __shfl_xor_sync(0xffffffffu, cs0[nj], 8);
    cs0[nj] += __shfl_xor_sync(0xffffffffu, cs0[nj], 16);
    cs1[nj] += __shfl_xor_sync(0xffffffffu, cs1[nj], 4);
    cs1[nj] += __shfl_xor_sync(0xffffffffu, cs1[nj], 8);
    cs1[nj] += __shfl_xor_sync(0xffffffffu, cs1[nj], 16);
  }
  if (qr == 0) {
    float* cp = colp + (wid & 3) * 128;
#pragma unroll
    for (int nj = 0; nj < 4; nj++) {
      cp[c0 + nj * 8 + 2 * qc] = cs0[nj];
      cp[c0 + nj * 8 + 2 * qc + 1] = cs1[nj];
    }
  }
}

// out_l: XL[c][w] += invrow[w] * (E @ V2)[w][c]. bf16 m16n8k16, K=128 (pairs along v). 
__device__ __forceinline__ void gemm_out_l(
    const uint32_t* __restrict__ Eb, const uint32_t* __restrict__ V2b,
    float* __restrict__ XL, const float* __restrict__ invrow, int wid, int qr, int qc) {
  const int r0 = (wid & 3) * 32;
  const int c0 = (wid >> 2) * 16;
  float acc[2][2][4];
#pragma unroll
  for (int mi = 0; mi < 2; mi++)
#pragma unroll
    for (int nj = 0; nj < 2; nj++)
#pragma unroll
      for (int e = 0; e < 4; e++) acc[mi][nj][e] = 0.f;

#pragma unroll
  for (int k0 = 0; k0 < 128; k0 += 16) {
    const int kw = (k0 >> 1) + qc;
    uint32_t af[2][4];
#pragma unroll
    for (int mi = 0; mi < 2; mi++) {
      const int r = r0 + mi * 16 + qr;
      af[mi][0] = Eb[r * PB + kw];
      af[mi][1] = Eb[(r + 8) * PB + kw];
      af[mi][2] = Eb[r * PB + kw + 4];
      af[mi][3] = Eb[(r + 8) * PB + kw + 4];
    }
    uint32_t bf[2][2];
#pragma unroll
    for (int nj = 0; nj < 2; nj++) {
      const int cc = c0 + nj * 8 + qr;
      bf[nj][0] = V2b[cc * PB + kw];
      bf[nj][1] = V2b[cc * PB + kw + 4];
    }
#pragma unroll
    for (int mi = 0; mi < 2; mi++)
#pragma unroll
      for (int nj = 0; nj < 2; nj++)
        mma16(acc[mi][nj], af[mi][0], af[mi][1], af[mi][2], af[mi][3], bf[nj][0], bf[nj][1]);
  }

#pragma unroll
  for (int mi = 0; mi < 2; mi++) {
    const int ra = r0 + mi * 16 + qr;
    const float ir0 = invrow[ra], ir1 = invrow[ra + 8];
#pragma unroll
    for (int nj = 0; nj < 2; nj++) {
      const int cc = c0 + nj * 8 + 2 * qc;
      XL[cc * PW + ra] += acc[mi][nj][0] * ir0;
      XL[(cc + 1) * PW + ra] += acc[mi][nj][1] * ir0;
      XL[cc * PW + ra + 8] += acc[mi][nj][2] * ir1;
      XL[(cc + 1) * PW + ra + 8] += acc[mi][nj][3] * ir1;
    }
  }
}

// out_h: out_h^T[c][w] = sum_u V1[u][c] * E[u][w]. A = V1b (pairs along u),
// B = Ebt[w][u/2] (pairs along u). Ebt split: rows 0-63 in EbtLo, 64-127 in EbtHi.
__device__ __forceinline__ void gemm_out_h(
    const uint32_t* __restrict__ EbtLo, const uint32_t* __restrict__ EbtHi,
    const uint32_t* __restrict__ V1b, float* __restrict__ XH,
    const float* __restrict__ invcol, int wid, int qr, int qc) {
  const int r0 = (wid & 3) * 16;   // c
  const int c0 = (wid >> 2) * 32;  // w
  const uint32_t* Ebt = (c0 >= 64) ? EbtHi : EbtLo;
  const int cbase = c0 & 63;
  float acc[4][4];
#pragma unroll
  for (int nj = 0; nj < 4; nj++)
#pragma unroll
    for (int e = 0; e < 4; e++) acc[nj][e] = 0.f;

#pragma unroll
  for (int k0 = 0; k0 < 128; k0 += 16) {
    const int kw = (k0 >> 1) + qc;
    const int rr = r0 + qr;
    uint32_t a0 = V1b[rr * PB + kw];
    uint32_t a1 = V1b[(rr + 8) * PB + kw];
    uint32_t a2 = V1b[rr * PB + kw + 4];
    uint32_t a3 = V1b[(rr + 8) * PB + kw + 4];
    uint32_t bf[4][2];
#pragma unroll
    for (int nj = 0; nj < 4; nj++) {
      const int cc = cbase + nj * 8 + qr;
      bf[nj][0] = Ebt[cc * PB + kw];
      bf[nj][1] = Ebt[cc * PB + kw + 4];
    }
#pragma unroll
    for (int nj = 0; nj < 4; nj++)
      mma16(acc[nj], a0, a1, a2, a3, bf[nj][0], bf[nj][1]);
  }

  const int ra = r0 + qr;  // c
#pragma unroll
  for (int nj = 0; nj < 4; nj++) {
    const int w0 = c0 + nj * 8 + 2 * qc;
    const int w1 = w0 + 1;
    XH[ra * PW + w0] += acc[nj][0] * invcol[w0];
    XH[ra * PW + w1] += acc[nj][1] * invcol[w1];
    XH[(ra + 8) * PW + w0] += acc[nj][2] * invcol[w0];
    XH[(ra + 8) * PW + w1] += acc[nj][3] * invcol[w1];
  }
}

__global__ __launch_bounds__(NTHR)
void scam_kernel(const float* __restrict__ x_l, const float* __restrict__ x_h,
                 const float* __restrict__ g1, const float* __restrict__ b1,
                 const float* __restrict__ g2, const float* __restrict__ b2,
                 const float* __restrict__ Wq, const float* __restrict__ Wk,
                 const float* __restrict__ Wv1, const float* __restrict__ Wv2,
                 float* __restrict__ out_l, float* __restrict__ out_h) {
  extern __shared__ float sm[];
  float* XL = sm;                    // [64][PW] c-major fp32 residual + out stage
  float* XH = XL + 64 * PW;
  float* QV1 = XH + 64 * PW;         // Q w-major [128][PX]; later V1b + EbtLo
  float* KV2 = QV1 + 128 * PX;       // K; later V2b + EbtHi
  uint32_t* Eb = (uint32_t*)(KV2 + 128 * PX);  // [128][PB] bf16x2 exp(attn)
  float* WB = (float*)(Eb + 128 * PB);         // [64][PX] weight staging
  float* rowp = WB + 64 * PX;        // [4][128]
  float* colp = rowp + 512;          // [4][128]
  float* meanl = colp + 512;
  float* rstdl = meanl + 128;
  float* meanh = rstdl + 128;
  float* rstdh = meanh + 128;
  float* t1 = rstdh + 128;
  float* t2 = t1 + 64;
  float* invrow = t2 + 64;
  float* invcol = invrow + 128;
  uint32_t* V1b = (uint32_t*)QV1;      // [64][PB] bf16x2 (overwrites Q lo half)
  uint32_t* V2b = (uint32_t*)KV2;      // [64][PB] bf16x2 (overwrites K lo half)
  uint32_t* EbtLo = V1b + 64 * PB;     // Ebt rows 0-63  (Q hi half)
  uint32_t* EbtHi = V2b + 64 * PB;     // Ebt rows 64-127 (K hi half)

  const int tid = threadIdx.x;
  const int lane = tid & 31;
  const int wid = tid >> 5;
  const int qr = lane >> 2;
  const int qc = lane & 3;
  const int bh = blockIdx.x;
  const int b = bh >> 7;
  const int h = bh & 127;
  const size_t planeoff = ((size_t)b * kC * kH + (size_t)h) * kW;

  // ---- P1: stage x (c-major float4, conflict-free, coalesced) ----
  for (int i = tid; i < kC * (kW / 4); i += NTHR) {
    const int c = i >> 5;
    const int w4 = (i & 31) * 4;
    const size_t goff = planeoff + (size_t)c * PLANE + w4;
    *(float4*)(XL + c * PW + w4) = *(const float4*)(x_l + goff);
    *(float4*)(XH + c * PW + w4) = *(const float4*)(x_h + goff);
  }
  __syncthreads();

  // ---- P2: LN stats (2 thr/row) + stage Wq ----
  {
    const int rowid = tid >> 1;
    const int r = rowid & 127;
    const int half = tid & 1;
    const float* src = (rowid < 128 ? XL : XH) + half * 32 * PW + r;
    float s = 0.f, s2 = 0.f;
#pragma unroll
    for (int c = 0; c < 32; c++) {
      const float v = src[c * PW];
      s += v;
      s2 = fmaf(v, v, s2);
    }
    s += __shfl_xor_sync(0xffffffffu, s, 1);
    s2 += __shfl_xor_sync(0xffffffffu, s2, 1);
    if (half == 0) {
      const float m = s * (1.f / 64.f);
      const float var = fmaf(-m, m, s2 * (1.f / 64.f));
      const float rs = rsqrtf(var + 1e-5f);
      if (rowid < 128) { meanl[r] = m; rstdl[r] = rs; }
      else             { meanh[r] = m; rstdh[r] = rs; }
    }
  }
  load_weight_fold(Wq, g1, b1, WB, t1, t2, tid);
  __syncthreads();

  gemm_qk(XL, WB, QV1, wid, qr, qc, meanl, rstdl, t1, t2);
  __syncthreads();

  load_weight_fold(Wk, g2, b2, WB, t1, t2, tid);
  __syncthreads();

  gemm_qk(XH, WB, KV2, wid, qr, qc, meanh, rstdh, t1, t2);
  __syncthreads();

  // ---- P4: E = exp(QK^T/8) -> bf16x2 + partials; stage Wv1 same phase ----
  gemm_s(QV1, KV2, Eb, rowp, colp, wid, qr, qc);
  load_weight_raw(Wv1, WB, tid);
  __syncthreads();

  // ---- P5a: inverses; transpose Eb -> Ebt (into Q/K hi halves); V1 gemm ----
  if (tid < 128) {
    invrow[tid] = 1.f / (rowp[tid] + rowp[128 + tid] + rowp[256 + tid] + rowp[384 + tid]);
  } else if (tid < 256) {
    const int c = tid - 128;
    invcol[c] = 1.f / (colp[c] + colp[128 + c] + colp[256 + c] + colp[384 + c]);
  }
  {
    // lane mapping: r' = lane>>2 (+8*(wid&7)), cidx = lane&3 (+4*(wid>>3), +8*cj)
    const int rp = (lane >> 2) + 8 * (wid & 7);        // 0..63
    const int ci0 = (lane & 3) + 4 * (wid >> 3);       // 0..7
#pragma unroll
    for (int cj = 0; cj < 8; cj++) {
      const int cidx = ci0 + 8 * cj;                   // 0..63
      const uint32_t w0 = Eb[(2 * rp) * PB + cidx];
      const uint32_t w1 = Eb[(2 * rp + 1) * PB + cidx];
      uint32_t* base = (cidx < 32) ? EbtLo : EbtHi;
      const int srow = (2 * cidx) & 63;
      base[srow * PB + rp] = __byte_perm(w0, w1, 0x5410);
      base[(srow + 1) * PB + rp] = __byte_perm(w0, w1, 0x7632);
    }
  }
  gemm_vT(XL, WB, V1b, wid, qr, qc);
  __syncthreads();

  load_weight_raw(Wv2, WB, tid);
  __syncthreads();

  gemm_vT(XH, WB, V2b, wid, qr, qc);
  __syncthreads();

  // ---- P6: out gemms (bf16 m16n8k16), smem epilogues into XL/XH ----
  gemm_out_l(Eb, V2b, XL, invrow, wid, qr, qc);
  gemm_out_h(EbtLo, EbtHi, V1b, XH, invcol, wid, qr, qc);
  __syncthreads();

  // ---- P7: writeout (conflict-free LDS.128, coalesced STG) ----
  for (int i = tid; i < kC * (kW / 4); i += NTHR) {
    const int c = i >> 5;
    const int w4 = (i & 31) * 4;
    const size_t goff = planeoff + (size_t)c * PLANE + w4;
    *(float4*)(out_l + goff) = *(const float4*)(XL + c * PW + w4);
    *(float4*)(out_h + goff) = *(const float4*)(XH + c * PW + w4);
  }
}

}  // namespace

extern "C" void kernel_launch(void* const* d_in, const int* in_sizes, int n_in,
                              void* d_out, int out_size) {
  const float* x_l = (const float*)d_in[0];
  const float* x_h = (const float*)d_in[1];
  const float* g1 = (const float*)d_in[2];
  const float* b1 = (const float*)d_in[3];
  const float* g2 = (const float*)d_in[4];
  const float* b2 = (const float*)d_in[5];
  const float* Wq = (const float*)d_in[6];
  const float* Wk = (const float*)d_in[7];
  const float* Wv1 = (const float*)d_in[8];
  const float* Wv2 = (const float*)d_in[9];

  float* out = (float*)d_out;
  float* out_l = out;
  float* out_h = out + (size_t)kB * kC * kH * kW;

  const size_t smem = (size_t)SMEM_FLOATS * sizeof(float);  // ~199 KB
  cudaFuncSetAttribute(scam_kernel, cudaFuncAttributeMaxDynamicSharedMemorySize, (int)smem);
  scam_kernel<<<kB * kH, NTHR, smem>>>(x_l, x_h, g1, b1, g2, b2, Wq, Wk, Wv1, Wv2,
                                       out_l, out_h);
}